// round 9
// baseline (speedup 1.0000x reference)
#include <cuda_runtime.h>

#define NN 2048
#define GRID 256
#define LOG2F_ 0.69314718055994530942f

typedef unsigned long long ull;

// Scratch (__device__ globals; no cudaMalloc allowed)
__device__ __align__(16) float g_M1T[32 * NN];   // [u][n] averaged em1, transposed
__device__ __align__(16) ull   g_A2[32 * NN];    // [u][n] averaged em2, DUP pairs (v,v)
__device__ float g_partial[4 * NN];              // softplus row-sums per j-quarter
__device__ float g_diag[NN];                     // raw u_ii
__device__ unsigned g_bar_cnt = 0;               // epoch barrier counter (monotone)

// ---- packed f32x2 helpers (FFMA2 only reachable via PTX fma.rn.f32x2) ----
__device__ __forceinline__ ull pack2(float x, float y) {
    ull r;
    asm("mov.b64 %0, {%1, %2};" : "=l"(r) : "r"(__float_as_uint(x)), "r"(__float_as_uint(y)));
    return r;
}
__device__ __forceinline__ void unpack2(ull v, float& x, float& y) {
    unsigned lo, hi;
    asm("mov.b64 {%0, %1}, %2;" : "=r"(lo), "=r"(hi) : "l"(v));
    x = __uint_as_float(lo); y = __uint_as_float(hi);
}
__device__ __forceinline__ ull ffma2(ull a, ull b, ull c) {
    ull d;
    asm("fma.rn.f32x2 %0, %1, %2, %3;" : "=l"(d) : "l"(a), "l"(b), "l"(c));
    return d;
}

// stable softplus(x) = max(x,0) + log(1 + exp(-|x|))
__device__ __forceinline__ float softplus_f(float x) {
    float a = fabsf(x);
    float l = __logf(1.f + __expf(-a));
    return fmaxf(x, 0.f) + l;
}

// Grid-wide epoch barrier. Safe across CUDA-graph replays without reset:
// every launch performs exactly 2 barriers with all GRID blocks, so
// epoch = old/GRID is globally consistent; wraparound-safe compare.
__device__ __forceinline__ void grid_barrier() {
    __syncthreads();
    __threadfence();
    if (threadIdx.x == 0) {
        unsigned old = atomicAdd(&g_bar_cnt, 1u);
        unsigned target = (old / GRID + 1u) * GRID;
        while ((int)(*(volatile unsigned*)&g_bar_cnt - target) < 0)
            __nanosleep(20);
    }
    __syncthreads();
    __threadfence();
}

// ---- shared memory union (static, < 48KB) ----
// embed phase: sP1 16K | sP2 8K | sb1/sb2 256B | sp1 10K | sp2 10K = 44.3KB
// jsd phase:   sA2 8K | sB 32K = 40KB
#define SM_SP1   0
#define SM_SP2   16384
#define SM_SB1   24576
#define SM_SB2   24704
#define SM_P1    24832
#define SM_P2    35072
#define SM_TOTAL 45312
#define SMJ_A2   0
#define SMJ_B    8192

__global__ void __launch_bounds__(256, 2) fused_kernel(
    const float* __restrict__ state, const float* __restrict__ action,
    const float* __restrict__ W1, const float* __restrict__ b1,
    const float* __restrict__ W2, const float* __restrict__ b2,
    float* __restrict__ out) {
    __shared__ __align__(16) char smem_raw[SM_TOTAL];

    const int tid = threadIdx.x;
    const int blk = blockIdx.x;

    // =====================================================================
    // PHASE 1: embeddings + leaky_relu + agent-mean. Block owns 8 samples
    // (two 4-sample groups accumulated simultaneously -> 2x LDG MLP).
    // Thread = (nl 0..3, kq 0..3, uh 0..15); K split x4, partials via smem.
    // =====================================================================
    {
        ull   (*sP1)[32] = (ull (*)[32])(smem_raw + SM_SP1);
        ull   (*sP2)[32] = (ull (*)[32])(smem_raw + SM_SP2);
        float *sb1 = (float*)(smem_raw + SM_SB1);
        float *sb2 = (float*)(smem_raw + SM_SB2);
        float (*sp1)[4][5][32] = (float (*)[4][5][32])(smem_raw + SM_P1);
        float (*sp2)[4][5][32] = (float (*)[4][5][32])(smem_raw + SM_P2);

        #pragma unroll
        for (int i = 0; i < 8; i++) {                // paired W1: (w[2k],w[2k+1]) per u
            int idx = tid + i * 256;                 // 0..2047
            int k2 = idx >> 5, u = idx & 31;
            sP1[k2][u] = pack2(W1[k2 * 64 + u], W1[k2 * 64 + 32 + u]);
        }
        #pragma unroll
        for (int i = 0; i < 4; i++) {                // paired W2
            int idx = tid + i * 256;                 // 0..1023
            int k2 = idx >> 5, u = idx & 31;
            sP2[k2][u] = pack2(W2[k2 * 64 + u], W2[k2 * 64 + 32 + u]);
        }
        if (tid < 32) { sb1[tid] = b1[tid]; sb2[tid] = b2[tid]; }
        __syncthreads();

        const int nl = tid >> 6, kq = (tid >> 4) & 3, uh = tid & 15;
        const int n8 = blk * 8;
        const int n0 = n8 + nl;                      // group 0 sample
        // group 1 sample = n0 + 4

        // ---------------- GEMM1: state @ W1, K-quarter (32 of 128) --------
        {
            const float* base0 = state + (size_t)n0 * 640 + kq * 32;
            const float* base1 = base0 + 4 * 640;
            ull a0[5][2], a1[5][2];
            #pragma unroll
            for (int a = 0; a < 5; a++) {
                a0[a][0] = a0[a][1] = 0ull;
                a1[a][0] = a1[a][1] = 0ull;
            }
            #pragma unroll
            for (int k4 = 0; k4 < 8; k4++) {
                ulonglong2 x0[5], x1[5];
                #pragma unroll
                for (int a = 0; a < 5; a++)
                    x0[a] = *(const ulonglong2*)(base0 + a * 128 + k4 * 4);
                #pragma unroll
                for (int a = 0; a < 5; a++)
                    x1[a] = *(const ulonglong2*)(base1 + a * 128 + k4 * 4);
                const int k2 = kq * 16 + k4 * 2;
                ulonglong2 w0 = *(const ulonglong2*)&sP1[k2][2 * uh];
                ulonglong2 w1 = *(const ulonglong2*)&sP1[k2 + 1][2 * uh];
                #pragma unroll
                for (int a = 0; a < 5; a++) {
                    a0[a][0] = ffma2(x0[a].x, w0.x, a0[a][0]);
                    a0[a][0] = ffma2(x0[a].y, w1.x, a0[a][0]);
                    a0[a][1] = ffma2(x0[a].x, w0.y, a0[a][1]);
                    a0[a][1] = ffma2(x0[a].y, w1.y, a0[a][1]);
                    a1[a][0] = ffma2(x1[a].x, w0.x, a1[a][0]);
                    a1[a][0] = ffma2(x1[a].y, w1.x, a1[a][0]);
                    a1[a][1] = ffma2(x1[a].x, w0.y, a1[a][1]);
                    a1[a][1] = ffma2(x1[a].y, w1.y, a1[a][1]);
                }
            }
            #pragma unroll
            for (int g = 0; g < 2; g++) {            // group partials + finalize
                #pragma unroll
                for (int a = 0; a < 5; a++) {
                    float p0, p1, q0, q1;
                    unpack2(g ? a1[a][0] : a0[a][0], p0, p1);
                    unpack2(g ? a1[a][1] : a0[a][1], q0, q1);
                    *(float2*)&sp1[nl][kq][a][2 * uh] = make_float2(p0 + p1, q0 + q1);
                }
                __syncthreads();
                if (tid < 128) {                     // fu = tid>>2, fnl = tid&3
                    const int fu = tid >> 2, fnl = tid & 3;
                    const int fn = n8 + g * 4 + fnl;
                    float m = 0.f;
                    #pragma unroll
                    for (int a = 0; a < 5; a++) {
                        float v = sb1[fu];
                        #pragma unroll
                        for (int q = 0; q < 4; q++) v += sp1[fnl][q][a][fu];
                        m += (v > 0.f) ? v : 0.01f * v;   // leaky_relu(0.01)
                    }
                    g_M1T[fu * NN + fn] = 0.2f * m;
                }
                __syncthreads();
            }
        }

        // ---------------- GEMM2: action @ W2, K-quarter (16 of 64) --------
        {
            const float* base0 = action + (size_t)n0 * 320 + kq * 16;
            const float* base1 = base0 + 4 * 320;
            ull a0[5][2], a1[5][2];
            #pragma unroll
            for (int a = 0; a < 5; a++) {
                a0[a][0] = a0[a][1] = 0ull;
                a1[a][0] = a1[a][1] = 0ull;
            }
            #pragma unroll
            for (int k4 = 0; k4 < 4; k4++) {
                ulonglong2 x0[5], x1[5];
                #pragma unroll
                for (int a = 0; a < 5; a++)
                    x0[a] = *(const ulonglong2*)(base0 + a * 64 + k4 * 4);
                #pragma unroll
                for (int a = 0; a < 5; a++)
                    x1[a] = *(const ulonglong2*)(base1 + a * 64 + k4 * 4);
                const int k2 = kq * 8 + k4 * 2;
                ulonglong2 w0 = *(const ulonglong2*)&sP2[k2][2 * uh];
                ulonglong2 w1 = *(const ulonglong2*)&sP2[k2 + 1][2 * uh];
                #pragma unroll
                for (int a = 0; a < 5; a++) {
                    a0[a][0] = ffma2(x0[a].x, w0.x, a0[a][0]);
                    a0[a][0] = ffma2(x0[a].y, w1.x, a0[a][0]);
                    a0[a][1] = ffma2(x0[a].x, w0.y, a0[a][1]);
                    a0[a][1] = ffma2(x0[a].y, w1.y, a0[a][1]);
                    a1[a][0] = ffma2(x1[a].x, w0.x, a1[a][0]);
                    a1[a][0] = ffma2(x1[a].y, w1.x, a1[a][0]);
                    a1[a][1] = ffma2(x1[a].x, w0.y, a1[a][1]);
                    a1[a][1] = ffma2(x1[a].y, w1.y, a1[a][1]);
                }
            }
            #pragma unroll
            for (int g = 0; g < 2; g++) {
                #pragma unroll
                for (int a = 0; a < 5; a++) {
                    float p0, p1, q0, q1;
                    unpack2(g ? a1[a][0] : a0[a][0], p0, p1);
                    unpack2(g ? a1[a][1] : a0[a][1], q0, q1);
                    *(float2*)&sp2[nl][kq][a][2 * uh] = make_float2(p0 + p1, q0 + q1);
                }
                __syncthreads();
                if (tid < 128) {
                    const int fu = tid >> 2, fnl = tid & 3;
                    const int fn = n8 + g * 4 + fnl;
                    float m = 0.f;
                    #pragma unroll
                    for (int a = 0; a < 5; a++) {
                        float v = sb2[fu];
                        #pragma unroll
                        for (int q = 0; q < 4; q++) v += sp2[fnl][q][a][fu];
                        m += (v > 0.f) ? v : 0.01f * v;
                    }
                    float s2 = 0.2f * m;
                    g_A2[fu * NN + fn] = pack2(s2, s2);   // pre-duplicated pair
                }
                __syncthreads();
            }
        }
    }

    grid_barrier();   // all embeddings visible

    // =====================================================================
    // PHASE 2: fused GEMM (u[i,j]=M2[i].M1[j], K=32) + softplus row-sums.
    // Tile = blk: 64 i-tiles(32 rows) x 4 j-quarters(512 cols).
    // Warp = 4 i-rows (A broadcast); thread tile 4i x 8j, conflict-free LDS.
    // =====================================================================
    {
        ull   (*sA2)[32] = (ull (*)[32])(smem_raw + SMJ_A2);
        float (*sB)[256] = (float (*)[256])(smem_raw + SMJ_B);

        const int ib = blk >> 2, q = blk & 3;
        const int i0 = ib * 32, jq = q * 512;
        const int ti = tid >> 5, tj = tid & 31;

        #pragma unroll
        for (int t = 0; t < 4; t++) {                // stage A dup pairs
            int idx = tid + t * 256;                 // 0..1023
            int u = idx >> 5, ii = idx & 31;
            sA2[u][ii] = g_A2[u * NN + i0 + ii];
        }
        float4 st[8];
        #pragma unroll
        for (int t = 0; t < 8; t++) {                // stage B chunk 0
            int idx = tid + t * 256;
            int u = idx >> 6, f = (idx & 63) * 4;
            st[t] = *(const float4*)&g_M1T[u * NN + jq + f];
        }
        #pragma unroll
        for (int t = 0; t < 8; t++) {
            int idx = tid + t * 256;
            int u = idx >> 6, f = (idx & 63) * 4;
            *(float4*)&sB[u][f] = st[t];
        }
        __syncthreads();

        float rowsum[4] = {0.f, 0.f, 0.f, 0.f};
        const bool qmatch = (q == (i0 >> 9));
        const int dc = (i0 & 511) >> 8;

        #pragma unroll
        for (int c = 0; c < 2; c++) {
            if (c == 0) {                            // prefetch chunk 1
                #pragma unroll
                for (int t = 0; t < 8; t++) {
                    int idx = tid + t * 256;
                    int u = idx >> 6, f = (idx & 63) * 4;
                    st[t] = *(const float4*)&g_M1T[u * NN + jq + 256 + f];
                }
            }

            ull acc[4][4];
            #pragma unroll
            for (int r = 0; r < 4; r++)
                #pragma unroll
                for (int p = 0; p < 4; p++) acc[r][p] = 0ull;

            #pragma unroll 8
            for (int u = 0; u < 32; u++) {
                ulonglong2 ad0 = *(const ulonglong2*)&sA2[u][ti * 4];
                ulonglong2 ad1 = *(const ulonglong2*)&sA2[u][ti * 4 + 2];
                ulonglong2 b0  = *(const ulonglong2*)&sB[u][tj * 4];
                ulonglong2 b1  = *(const ulonglong2*)&sB[u][128 + tj * 4];
                acc[0][0] = ffma2(ad0.x, b0.x, acc[0][0]);
                acc[0][1] = ffma2(ad0.x, b0.y, acc[0][1]);
                acc[0][2] = ffma2(ad0.x, b1.x, acc[0][2]);
                acc[0][3] = ffma2(ad0.x, b1.y, acc[0][3]);
                acc[1][0] = ffma2(ad0.y, b0.x, acc[1][0]);
                acc[1][1] = ffma2(ad0.y, b0.y, acc[1][1]);
                acc[1][2] = ffma2(ad0.y, b1.x, acc[1][2]);
                acc[1][3] = ffma2(ad0.y, b1.y, acc[1][3]);
                acc[2][0] = ffma2(ad1.x, b0.x, acc[2][0]);
                acc[2][1] = ffma2(ad1.x, b0.y, acc[2][1]);
                acc[2][2] = ffma2(ad1.x, b1.x, acc[2][2]);
                acc[2][3] = ffma2(ad1.x, b1.y, acc[2][3]);
                acc[3][0] = ffma2(ad1.y, b0.x, acc[3][0]);
                acc[3][1] = ffma2(ad1.y, b0.y, acc[3][1]);
                acc[3][2] = ffma2(ad1.y, b1.x, acc[3][2]);
                acc[3][3] = ffma2(ad1.y, b1.y, acc[3][3]);
            }

            const bool isdc = qmatch && (c == dc);
            const int cbase = jq + c * 256;
            #pragma unroll
            for (int r = 0; r < 4; r++) {
                const int ig = i0 + ti * 4 + r;
                float s = 0.f;
                #pragma unroll
                for (int p = 0; p < 4; p++) {
                    float x0, x1;
                    unpack2(acc[r][p], x0, x1);
                    if (isdc) {
                        int col = cbase + ((p < 2) ? (tj * 4 + p * 2)
                                                   : (128 + tj * 4 + (p - 2) * 2));
                        if (col == ig)     g_diag[ig] = x0;
                        if (col + 1 == ig) g_diag[ig] = x1;
                    }
                    s += softplus_f(x0) + softplus_f(x1);
                }
                rowsum[r] += s;
            }

            if (c == 0) {
                __syncthreads();
                #pragma unroll
                for (int t = 0; t < 8; t++) {
                    int idx = tid + t * 256;
                    int u = idx >> 6, f = (idx & 63) * 4;
                    *(float4*)&sB[u][f] = st[t];
                }
                __syncthreads();
            }
        }

        #pragma unroll
        for (int r = 0; r < 4; r++) {                // rows within one warp
            float v = rowsum[r];
            v += __shfl_down_sync(0xffffffffu, v, 16);
            v += __shfl_down_sync(0xffffffffu, v, 8);
            v += __shfl_down_sync(0xffffffffu, v, 4);
            v += __shfl_down_sync(0xffffffffu, v, 2);
            v += __shfl_down_sync(0xffffffffu, v, 1);
            if (tj == 0) g_partial[q * NN + i0 + ti * 4 + r] = v;
        }
    }

    grid_barrier();   // all partials + diag visible

    // =====================================================================
    // PHASE 3: finalize loss/MI (blocks 0..7 cover 2048 rows).
    // =====================================================================
    if (blk < 8) {
        const int i = blk * 256 + tid;
        float tot = g_partial[i] + g_partial[NN + i]
                  + g_partial[2 * NN + i] + g_partial[3 * NN + i];  // incl. diag sp
        float ud  = g_diag[i];
        float spd = softplus_f(ud);
        float Eneg = (tot - spd - 2047.f * LOG2F_) * (1.f / 2047.f);
        float Epos = LOG2F_ - spd + ud;              // = log2 - softplus(-u_ii)
        out[i]      = Eneg - Epos;                   // loss
        out[NN + i] = Epos;                          // MI
    }
}

extern "C" void kernel_launch(void* const* d_in, const int* in_sizes, int n_in,
                              void* d_out, int out_size) {
    const float* state  = (const float*)d_in[0];
    const float* action = (const float*)d_in[1];
    const float* W1     = (const float*)d_in[2];
    const float* b1     = (const float*)d_in[3];
    const float* W2     = (const float*)d_in[4];
    const float* b2     = (const float*)d_in[5];
    float* out = (float*)d_out;

    fused_kernel<<<GRID, 256>>>(state, action, W1, b1, W2, b2, out);
}

// round 10
// speedup vs baseline: 1.0082x; 1.0082x over previous
#include <cuda_runtime.h>

#define NN 2048
#define LOG2F_ 0.69314718055994530942f

typedef unsigned long long ull;

// Scratch (__device__ globals; no cudaMalloc allowed)
__device__ __align__(16) float g_M1T[32 * NN];   // [u][n] averaged em1, transposed
__device__ __align__(16) ull   g_A2[32 * NN];    // [u][n] averaged em2, DUP pairs (v,v)
__device__ float g_partial[4 * NN];              // softplus row-sums per j-quarter
__device__ float g_diag[NN];                     // raw u_ii
__device__ unsigned g_ticket = 0;                // last-block ticket (monotone, %256)

// ---- packed f32x2 helpers (FFMA2 only reachable via PTX fma.rn.f32x2) ----
__device__ __forceinline__ ull pack2(float x, float y) {
    ull r;
    asm("mov.b64 %0, {%1, %2};" : "=l"(r) : "r"(__float_as_uint(x)), "r"(__float_as_uint(y)));
    return r;
}
__device__ __forceinline__ void unpack2(ull v, float& x, float& y) {
    unsigned lo, hi;
    asm("mov.b64 {%0, %1}, %2;" : "=r"(lo), "=r"(hi) : "l"(v));
    x = __uint_as_float(lo); y = __uint_as_float(hi);
}
__device__ __forceinline__ ull ffma2(ull a, ull b, ull c) {
    ull d;
    asm("fma.rn.f32x2 %0, %1, %2, %3;" : "=l"(d) : "l"(a), "l"(b), "l"(c));
    return d;
}

// stable softplus(x) = max(x,0) + log(1 + exp(-|x|))
__device__ __forceinline__ float softplus_f(float x) {
    float a = fabsf(x);
    float l = __logf(1.f + __expf(-a));
    return fmaxf(x, 0.f) + l;
}

// ---- embed smem layout (static 45.3KB, aliased regions) ----
// SM_IN: state (2560 f) during GEMM1, action (1280 f) during GEMM2.
// SM_PART shared between GEMM1 and GEMM2 partials (sequenced by syncs).
#define SM_IN    0
#define SM_SP1   10240
#define SM_SP2   26624
#define SM_PART  34816
#define SM_SB1   45056
#define SM_SB2   45184
#define SM_TOTAL 45312

// ---------------------------------------------------------------------------
// Kernel 1 (v5): embeddings + leaky_relu + agent-mean.
// All inputs staged through smem (coalesced LDG once, then LDS broadcast) so
// the inner loop is LDS(29cyc)+FFMA2 only -> latency exposure collapses.
// Grid 512 x 256thr; thread = (nl 0..3, kq 0..3, uh 0..15 -> units 2uh,2uh+1).
// K split x4; partials (linear in K) reduced via smem.
// ---------------------------------------------------------------------------
__global__ void __launch_bounds__(256) embed_kernel(
    const float* __restrict__ state, const float* __restrict__ action,
    const float* __restrict__ W1, const float* __restrict__ b1,
    const float* __restrict__ W2, const float* __restrict__ b2) {
    __shared__ __align__(16) char smem[SM_TOTAL];
    float* sIN = (float*)(smem + SM_IN);
    ull   (*sP1)[32] = (ull (*)[32])(smem + SM_SP1);
    ull   (*sP2)[32] = (ull (*)[32])(smem + SM_SP2);
    float (*spart)[4][5][32] = (float (*)[4][5][32])(smem + SM_PART);
    float* sb1 = (float*)(smem + SM_SB1);
    float* sb2 = (float*)(smem + SM_SB2);

    const int tid = threadIdx.x;

    #pragma unroll
    for (int i = 0; i < 8; i++) {                    // paired W1: (w[2k],w[2k+1]) per u
        int idx = tid + i * 256;                     // 0..2047
        int k2 = idx >> 5, u = idx & 31;
        sP1[k2][u] = pack2(W1[k2 * 64 + u], W1[k2 * 64 + 32 + u]);
    }
    #pragma unroll
    for (int i = 0; i < 4; i++) {                    // paired W2
        int idx = tid + i * 256;                     // 0..1023
        int k2 = idx >> 5, u = idx & 31;
        sP2[k2][u] = pack2(W2[k2 * 64 + u], W2[k2 * 64 + 32 + u]);
    }
    {   // stage state tile: 4 samples x 640 floats = 640 float4, coalesced
        const float4* sg = (const float4*)(state + (size_t)blockIdx.x * 2560);
        float4* si4 = (float4*)sIN;
        si4[tid]       = sg[tid];
        si4[tid + 256] = sg[tid + 256];
        if (tid < 128) si4[tid + 512] = sg[tid + 512];
    }
    if (tid < 32) { sb1[tid] = b1[tid]; sb2[tid] = b2[tid]; }
    __syncthreads();

    const int nl = tid >> 6, kq = (tid >> 4) & 3, uh = tid & 15;
    const int n8 = blockIdx.x * 4;

    // ---------------- GEMM1: state @ W1, K-quarter (32 of 128) ------------
    {
        const float* base = sIN + nl * 640 + kq * 32;
        ull acc[5][2];
        #pragma unroll
        for (int a = 0; a < 5; a++) { acc[a][0] = 0ull; acc[a][1] = 0ull; }

        #pragma unroll
        for (int k4 = 0; k4 < 8; k4++) {
            ulonglong2 x[5];
            #pragma unroll
            for (int a = 0; a < 5; a++)
                x[a] = *(const ulonglong2*)(base + a * 128 + k4 * 4);
            const int k2 = kq * 16 + k4 * 2;
            ulonglong2 w0 = *(const ulonglong2*)&sP1[k2][2 * uh];
            ulonglong2 w1 = *(const ulonglong2*)&sP1[k2 + 1][2 * uh];
            #pragma unroll
            for (int a = 0; a < 5; a++) {
                acc[a][0] = ffma2(x[a].x, w0.x, acc[a][0]);
                acc[a][0] = ffma2(x[a].y, w1.x, acc[a][0]);
                acc[a][1] = ffma2(x[a].x, w0.y, acc[a][1]);
                acc[a][1] = ffma2(x[a].y, w1.y, acc[a][1]);
            }
        }
        #pragma unroll
        for (int a = 0; a < 5; a++) {
            float x0, x1, y0, y1;
            unpack2(acc[a][0], x0, x1);
            unpack2(acc[a][1], y0, y1);
            *(float2*)&spart[nl][kq][a][2 * uh] = make_float2(x0 + x1, y0 + y1);
        }
    }
    __syncthreads();    // GEMM1 done reading sIN; partials complete

    // finalize1 (threads 0..127) + restage action over sIN (threads 128..255)
    if (tid < 128) {
        const int fu = tid >> 2, fnl = tid & 3;
        const int fn = n8 + fnl;
        float m = 0.f;
        #pragma unroll
        for (int a = 0; a < 5; a++) {
            float v = sb1[fu];
            #pragma unroll
            for (int q = 0; q < 4; q++) v += spart[fnl][q][a][fu];
            m += (v > 0.f) ? v : 0.01f * v;          // leaky_relu(0.01)
        }
        g_M1T[fu * NN + fn] = 0.2f * m;
    } else {
        const int t = tid - 128;                     // 0..127
        const float4* ag = (const float4*)(action + (size_t)blockIdx.x * 1280);
        float4* si4 = (float4*)sIN;                  // 320 float4
        si4[t]       = ag[t];
        si4[t + 128] = ag[t + 128];
        if (t < 64) si4[t + 256] = ag[t + 256];
    }
    __syncthreads();

    // ---------------- GEMM2: action @ W2, K-quarter (16 of 64) ------------
    {
        const float* base = sIN + nl * 320 + kq * 16;
        ull acc[5][2];
        #pragma unroll
        for (int a = 0; a < 5; a++) { acc[a][0] = 0ull; acc[a][1] = 0ull; }

        #pragma unroll
        for (int k4 = 0; k4 < 4; k4++) {
            ulonglong2 x[5];
            #pragma unroll
            for (int a = 0; a < 5; a++)
                x[a] = *(const ulonglong2*)(base + a * 64 + k4 * 4);
            const int k2 = kq * 8 + k4 * 2;
            ulonglong2 w0 = *(const ulonglong2*)&sP2[k2][2 * uh];
            ulonglong2 w1 = *(const ulonglong2*)&sP2[k2 + 1][2 * uh];
            #pragma unroll
            for (int a = 0; a < 5; a++) {
                acc[a][0] = ffma2(x[a].x, w0.x, acc[a][0]);
                acc[a][0] = ffma2(x[a].y, w1.x, acc[a][0]);
                acc[a][1] = ffma2(x[a].x, w0.y, acc[a][1]);
                acc[a][1] = ffma2(x[a].y, w1.y, acc[a][1]);
            }
        }
        __syncthreads();    // finalize1 done reading spart before overwrite
        #pragma unroll
        for (int a = 0; a < 5; a++) {
            float x0, x1, y0, y1;
            unpack2(acc[a][0], x0, x1);
            unpack2(acc[a][1], y0, y1);
            *(float2*)&spart[nl][kq][a][2 * uh] = make_float2(x0 + x1, y0 + y1);
        }
    }
    __syncthreads();

    if (tid < 128) {
        const int fu = tid >> 2, fnl = tid & 3;
        const int fn = n8 + fnl;
        float m = 0.f;
        #pragma unroll
        for (int a = 0; a < 5; a++) {
            float v = sb2[fu];
            #pragma unroll
            for (int q = 0; q < 4; q++) v += spart[fnl][q][a][fu];
            m += (v > 0.f) ? v : 0.01f * v;
        }
        float s2 = 0.2f * m;
        g_A2[fu * NN + fn] = pack2(s2, s2);          // pre-duplicated pair
    }
}

// ---------------------------------------------------------------------------
// Kernel 2 (v4): fused GEMM (u[i,j]=M2[i].M1[j], K=32) + softplus row-sums
// + last-block finalize (threadFenceReduction ticket; epoch-safe: grid==256,
// counter monotone across graph replays, old%256==255 marks each launch's
// last block). Tiling identical to R8 (measured good): grid 256 =
// 64 i-tiles(32 rows) x 4 j-quarters(512). Warp = 4 i-rows (A broadcast);
// thread tile 4i x 8j, conflict-free LDS.128.
// ---------------------------------------------------------------------------
__global__ void __launch_bounds__(256) jsd_kernel(float* __restrict__ out) {
    __shared__ __align__(16) ull sA2[32][32];        // 8 KB [u][ii] dup pairs
    __shared__ __align__(16) float sB[32][256];      // 32 KB chunk buffer
    __shared__ unsigned s_last;

    const int tid = threadIdx.x;
    const int ib = blockIdx.x >> 2, q = blockIdx.x & 3;
    const int i0 = ib * 32, jq = q * 512;
    const int ti = tid >> 5, tj = tid & 31;          // warp id = ti

    #pragma unroll
    for (int t = 0; t < 4; t++) {                    // stage A dup pairs
        int idx = tid + t * 256;                     // 0..1023
        int u = idx >> 5, ii = idx & 31;
        sA2[u][ii] = g_A2[u * NN + i0 + ii];
    }
    float4 st[8];
    #pragma unroll
    for (int t = 0; t < 8; t++) {                    // stage B chunk 0
        int idx = tid + t * 256;                     // 0..2047
        int u = idx >> 6, f = (idx & 63) * 4;
        st[t] = *(const float4*)&g_M1T[u * NN + jq + f];
    }
    #pragma unroll
    for (int t = 0; t < 8; t++) {
        int idx = tid + t * 256;
        int u = idx >> 6, f = (idx & 63) * 4;
        *(float4*)&sB[u][f] = st[t];
    }
    __syncthreads();

    float rowsum[4] = {0.f, 0.f, 0.f, 0.f};
    const bool qmatch = (q == (i0 >> 9));
    const int dc = (i0 & 511) >> 8;                  // diag chunk within quarter

    #pragma unroll
    for (int c = 0; c < 2; c++) {
        if (c == 0) {                                // prefetch chunk 1
            #pragma unroll
            for (int t = 0; t < 8; t++) {
                int idx = tid + t * 256;
                int u = idx >> 6, f = (idx & 63) * 4;
                st[t] = *(const float4*)&g_M1T[u * NN + jq + 256 + f];
            }
        }

        ull acc[4][4];
        #pragma unroll
        for (int r = 0; r < 4; r++)
            #pragma unroll
            for (int p = 0; p < 4; p++) acc[r][p] = 0ull;

        #pragma unroll 8
        for (int u = 0; u < 32; u++) {
            ulonglong2 ad0 = *(const ulonglong2*)&sA2[u][ti * 4];      // rows 0,1
            ulonglong2 ad1 = *(const ulonglong2*)&sA2[u][ti * 4 + 2];  // rows 2,3
            ulonglong2 b0  = *(const ulonglong2*)&sB[u][tj * 4];
            ulonglong2 b1  = *(const ulonglong2*)&sB[u][128 + tj * 4];
            acc[0][0] = ffma2(ad0.x, b0.x, acc[0][0]);
            acc[0][1] = ffma2(ad0.x, b0.y, acc[0][1]);
            acc[0][2] = ffma2(ad0.x, b1.x, acc[0][2]);
            acc[0][3] = ffma2(ad0.x, b1.y, acc[0][3]);
            acc[1][0] = ffma2(ad0.y, b0.x, acc[1][0]);
            acc[1][1] = ffma2(ad0.y, b0.y, acc[1][1]);
            acc[1][2] = ffma2(ad0.y, b1.x, acc[1][2]);
            acc[1][3] = ffma2(ad0.y, b1.y, acc[1][3]);
            acc[2][0] = ffma2(ad1.x, b0.x, acc[2][0]);
            acc[2][1] = ffma2(ad1.x, b0.y, acc[2][1]);
            acc[2][2] = ffma2(ad1.x, b1.x, acc[2][2]);
            acc[2][3] = ffma2(ad1.x, b1.y, acc[2][3]);
            acc[3][0] = ffma2(ad1.y, b0.x, acc[3][0]);
            acc[3][1] = ffma2(ad1.y, b0.y, acc[3][1]);
            acc[3][2] = ffma2(ad1.y, b1.x, acc[3][2]);
            acc[3][3] = ffma2(ad1.y, b1.y, acc[3][3]);
        }

        const bool isdc = qmatch && (c == dc);
        const int cbase = jq + c * 256;
        #pragma unroll
        for (int r = 0; r < 4; r++) {
            const int ig = i0 + ti * 4 + r;
            float s = 0.f;
            #pragma unroll
            for (int p = 0; p < 4; p++) {
                float x0, x1;
                unpack2(acc[r][p], x0, x1);
                if (isdc) {
                    int col = cbase + ((p < 2) ? (tj * 4 + p * 2)
                                               : (128 + tj * 4 + (p - 2) * 2));
                    if (col == ig)     g_diag[ig] = x0;   // single writer
                    if (col + 1 == ig) g_diag[ig] = x1;
                }
                s += softplus_f(x0) + softplus_f(x1);
            }
            rowsum[r] += s;
        }

        if (c == 0) {
            __syncthreads();
            #pragma unroll
            for (int t = 0; t < 8; t++) {
                int idx = tid + t * 256;
                int u = idx >> 6, f = (idx & 63) * 4;
                *(float4*)&sB[u][f] = st[t];
            }
            __syncthreads();
        }
    }

    #pragma unroll
    for (int r = 0; r < 4; r++) {                    // rows within one warp
        float v = rowsum[r];
        v += __shfl_down_sync(0xffffffffu, v, 16);
        v += __shfl_down_sync(0xffffffffu, v, 8);
        v += __shfl_down_sync(0xffffffffu, v, 4);
        v += __shfl_down_sync(0xffffffffu, v, 2);
        v += __shfl_down_sync(0xffffffffu, v, 1);
        if (tj == 0) g_partial[q * NN + i0 + ti * 4 + r] = v;
    }

    // ---- last-block finalize (threadFenceReduction pattern) ----
    __threadfence();                                 // publish partials + diag
    __syncthreads();
    if (tid == 0) {
        unsigned old = atomicAdd(&g_ticket, 1u);
        s_last = ((old & 255u) == 255u) ? 1u : 0u;   // grid == 256 exactly
    }
    __syncthreads();
    if (s_last) {
        __threadfence();                             // acquire others' writes
        #pragma unroll
        for (int r = 0; r < 8; r++) {
            const int i = tid + r * 256;
            float tot = g_partial[i] + g_partial[NN + i]
                      + g_partial[2 * NN + i] + g_partial[3 * NN + i];
            float ud  = g_diag[i];
            float spd = softplus_f(ud);
            float Eneg = (tot - spd - 2047.f * LOG2F_) * (1.f / 2047.f);
            float Epos = LOG2F_ - spd + ud;          // = log2 - softplus(-u_ii)
            out[i]      = Eneg - Epos;               // loss
            out[NN + i] = Epos;                      // MI
        }
    }
}

extern "C" void kernel_launch(void* const* d_in, const int* in_sizes, int n_in,
                              void* d_out, int out_size) {
    const float* state  = (const float*)d_in[0];
    const float* action = (const float*)d_in[1];
    const float* W1     = (const float*)d_in[2];
    const float* b1     = (const float*)d_in[3];
    const float* W2     = (const float*)d_in[4];
    const float* b2     = (const float*)d_in[5];
    float* out = (float*)d_out;

    embed_kernel<<<NN / 4, 256>>>(state, action, W1, b1, W2, b2);
    jsd_kernel<<<256, 256>>>(out);
}